// round 10
// baseline (speedup 1.0000x reference)
#include <cuda_runtime.h>

#define MAX_N 100000
#define D 64

// Scratch (device globals: sanctioned alternative to cudaMalloc)
__device__ float g_h[MAX_N * D];     // h = x @ W^T
__device__ float g_deg[MAX_N];
__device__ float g_dinv[MAX_N];
__device__ float g_Wt[D * D];        // W transposed: g_Wt[k*64+o] = W[o][k]

// ---------------------------------------------------------------------------
// 1) degree init: every node gets a self-loop -> deg starts at 1
// ---------------------------------------------------------------------------
__global__ void deg_init_kernel(int N4) {
    int i = blockIdx.x * blockDim.x + threadIdx.x;
    if (i < N4) ((float4*)g_deg)[i] = make_float4(1.f, 1.f, 1.f, 1.f);
}

// 2) accumulate in-degree over edge dst (edge_index is int32)
__global__ void deg_acc_kernel(const int* __restrict__ ei, int E) {
    int e = blockIdx.x * blockDim.x + threadIdx.x;
    if (e < E) atomicAdd(&g_deg[ei[E + e]], 1.0f);
}

// 3) transpose W once into gmem so gemm's smem fill is coalesced/conflict-free
__global__ void wt_kernel(const float* __restrict__ W) {
    int i = blockIdx.x * 256 + threadIdx.x;
    if (i < D * D) {
        int o = i >> 6, k = i & 63;
        g_Wt[k * D + o] = W[i];
    }
}

// ---------------------------------------------------------------------------
// 4) GEMM: h[n][o] = sum_k x[n][k] * W[o][k]
//    Lane mapping flipped vs R9: warp = 4 nodes/pass, lane owns
//    (node = l>>3, cols {c8*4..+3} and {32+c8*4..+3}), c8 = l&7.
//      - stores: 8 lanes cover a full 128B row-half -> perfectly coalesced
//        (R9 paid ~32 divergent wavefronts per node here)
//      - W LDS: 8 distinct float4 @16B stride = all 32 banks, 1 wf, serves
//        4 nodes
//      - x: swizzled smem, 4 broadcast addresses, conflict-free
//    4 passes/warp -> block covers 128 nodes (W fill amortized).
//    Epilogue: dinv, h, out = h*dinv^2 + b (covers poisoned out).
// ---------------------------------------------------------------------------
__global__ __launch_bounds__(256)
void gemm_kernel(const float* __restrict__ x,
                 const float* __restrict__ bias,
                 float* __restrict__ out, int N) {
    __shared__ float Ws[D * D];        // natural layout Ws[k*64+o]
    __shared__ float Xs[128 * D];      // 128-node tile, XOR-swizzled float4s

    int tid = threadIdx.x;

    for (int t = tid; t < D * D; t += 256) Ws[t] = g_Wt[t];

    int base = blockIdx.x * 128;
    int rows = N - base; if (rows > 128) rows = 128;
    const float4* xg = (const float4*)(x + (size_t)base * D);
    for (int t = tid; t < rows * 16; t += 256) {
        int r = t >> 4, j = t & 15;
        ((float4*)Xs)[r * 16 + (j ^ (r & 15))] = xg[t];
    }
    __syncthreads();

    int w    = tid >> 5;               // warp 0..7
    int lane = tid & 31;
    int nsub = lane >> 3;              // node sub-index 0..3
    int c8   = lane & 7;               // column octant -> cols c8*4 and 32+c8*4

    const float4* b4 = (const float4*)bias;
    float4 bb0 = __ldg(&b4[c8]);       // cols c8*4..+3
    float4 bb1 = __ldg(&b4[8 + c8]);   // cols 32+c8*4..+3

    const float4* Ws4 = (const float4*)Ws;

#pragma unroll 1
    for (int p = 0; p < 4; p++) {
        int rloc = w * 16 + p * 4 + nsub;    // 0..127
        int n = base + rloc;

        unsigned long long a0 = 0ULL, a1 = 0ULL, a2 = 0ULL, a3 = 0ULL;

        int sw = rloc & 15;
        const float4* xs = (const float4*)Xs + rloc * 16;

#pragma unroll 2
        for (int k4 = 0; k4 < 16; k4++) {
            float4 xv = xs[k4 ^ sw];         // broadcast x8, conflict-free x4
            float fx[4] = {xv.x, xv.y, xv.z, xv.w};
#pragma unroll
            for (int kk = 0; kk < 4; kk++) {
                int k = k4 * 4 + kk;
                unsigned long long xx;
                asm("mov.b64 %0, {%1, %1};" : "=l"(xx) : "f"(fx[kk]));
                // two conflict-free LDS.128: low half / high half of row k
                ulonglong2 wlo = ((const ulonglong2*)Ws4)[k * 8 + c8];      // cols c8*4..+3? (float4 pair)
                ulonglong2 whi = ((const ulonglong2*)Ws4)[k * 8 + 4 + (c8 >> 1)]; // placeholder - replaced below
                (void)wlo; (void)whi;
                // NOTE: use explicit float4-based ulonglong2 loads:
                const ulonglong2* wrow = (const ulonglong2*)(Ws + k * D);
                ulonglong2 w0 = wrow[c8];        // cols c8*4..c8*4+3   (16B)
                ulonglong2 w1 = wrow[8 + c8];    // cols 32+c8*4..+3    (16B)
                asm("fma.rn.f32x2 %0, %1, %2, %0;" : "+l"(a0) : "l"(xx), "l"(w0.x));
                asm("fma.rn.f32x2 %0, %1, %2, %0;" : "+l"(a1) : "l"(xx), "l"(w0.y));
                asm("fma.rn.f32x2 %0, %1, %2, %0;" : "+l"(a2) : "l"(xx), "l"(w1.x));
                asm("fma.rn.f32x2 %0, %1, %2, %0;" : "+l"(a3) : "l"(xx), "l"(w1.y));
            }
        }

        if (n < N) {
            float dv = rsqrtf(g_deg[n]);
            if (c8 == 0) g_dinv[n] = dv;
            float sl = dv * dv;

            float f0, f1, f2, f3, f4, f5, f6, f7;
            asm("mov.b64 {%0, %1}, %2;" : "=f"(f0), "=f"(f1) : "l"(a0));
            asm("mov.b64 {%0, %1}, %2;" : "=f"(f2), "=f"(f3) : "l"(a1));
            asm("mov.b64 {%0, %1}, %2;" : "=f"(f4), "=f"(f5) : "l"(a2));
            asm("mov.b64 {%0, %1}, %2;" : "=f"(f6), "=f"(f7) : "l"(a3));

            float4* hrow = (float4*)(g_h + (size_t)n * D);
            float4* orow = (float4*)(out + (size_t)n * D);
            hrow[c8]     = make_float4(f0, f1, f2, f3);   // coalesced across warp
            hrow[8 + c8] = make_float4(f4, f5, f6, f7);
            float4 ov0, ov1;
            ov0.x = fmaf(f0, sl, bb0.x);
            ov0.y = fmaf(f1, sl, bb0.y);
            ov0.z = fmaf(f2, sl, bb0.z);
            ov0.w = fmaf(f3, sl, bb0.w);
            ov1.x = fmaf(f4, sl, bb1.x);
            ov1.y = fmaf(f5, sl, bb1.y);
            ov1.z = fmaf(f6, sl, bb1.z);
            ov1.w = fmaf(f7, sl, bb1.w);
            orow[c8]     = ov0;
            orow[8 + c8] = ov1;
        }
    }
}

// ---------------------------------------------------------------------------
// 5) Edge scatter: out[dst] += h[src] * (dinv[src]*dinv[dst])
//    16 threads per edge, one float4 per thread, vector red.
//    (Measured 65 us — REDG LSU-rate floor for atomic formulation.)
// ---------------------------------------------------------------------------
__global__ __launch_bounds__(256)
void scatter_kernel(const int* __restrict__ ei,
                    float* __restrict__ out, int E) {
    long long gid = (long long)blockIdx.x * blockDim.x + threadIdx.x;
    int e = (int)(gid >> 4);
    int l = (int)(gid & 15);
    if (e >= E) return;

    int s = __ldg(&ei[e]);        // src
    int d = __ldg(&ei[E + e]);    // dst
    float norm = g_dinv[s] * g_dinv[d];

    float4 v = ((const float4*)g_h)[(size_t)s * 16 + l];
    v.x *= norm; v.y *= norm; v.z *= norm; v.w *= norm;

    float* o = out + ((size_t)d * D + l * 4);
    asm volatile("red.global.add.v4.f32 [%0], {%1, %2, %3, %4};"
                 :: "l"(o), "f"(v.x), "f"(v.y), "f"(v.z), "f"(v.w)
                 : "memory");
}

// ---------------------------------------------------------------------------
extern "C" void kernel_launch(void* const* d_in, const int* in_sizes, int n_in,
                              void* d_out, int out_size) {
    const float* x  = (const float*)d_in[0];
    const int*   ei = (const int*)d_in[1];
    const float* W  = (const float*)d_in[2];
    const float* b  = (const float*)d_in[3];
    float*       out = (float*)d_out;

    int N = in_sizes[0] / D;   // 100000
    int E = in_sizes[1] / 2;   // 1000000

    int N4 = N / 4;            // N divisible by 4
    deg_init_kernel<<<(N4 + 255) / 256, 256>>>(N4);
    deg_acc_kernel<<<(E + 255) / 256, 256>>>(ei, E);
    wt_kernel<<<16, 256>>>(W);
    gemm_kernel<<<(N + 127) / 128, 256>>>(x, b, out, N);

    long long total = (long long)E * 16;
    int nb_s = (int)((total + 255) / 256);
    scatter_kernel<<<nb_s, 256>>>(ei, out, E);
}

// round 12
// speedup vs baseline: 1.0449x; 1.0449x over previous
#include <cuda_runtime.h>
#include <cuda_bf16.h>
#include <cstdint>

#define MAX_N 100000
#define D 64
#define TILE 64            // rows per block
#define PITCH 36           // u32 pitch (32 k-pairs + 4 pad) -> conflict-free frags

// Scratch (device globals: sanctioned alternative to cudaMalloc)
__device__ float g_h[MAX_N * D];     // h = x @ W^T
__device__ float g_deg[MAX_N];
__device__ float g_dinv[MAX_N];

// ---------------------------------------------------------------------------
// 1) degree init: self-loop -> deg starts at 1
// ---------------------------------------------------------------------------
__global__ void deg_init_kernel(int N4) {
    int i = blockIdx.x * blockDim.x + threadIdx.x;
    if (i < N4) ((float4*)g_deg)[i] = make_float4(1.f, 1.f, 1.f, 1.f);
}

// 2) accumulate in-degree over edge dst (edge_index is int32)
__global__ void deg_acc_kernel(const int* __restrict__ ei, int E) {
    int e = blockIdx.x * blockDim.x + threadIdx.x;
    if (e < E) atomicAdd(&g_deg[ei[E + e]], 1.0f);
}

// ---------------------------------------------------------------------------
// helpers
// ---------------------------------------------------------------------------
__device__ __forceinline__ uint32_t pack_bf(float a, float b) {
    __nv_bfloat162 p = __floats2bfloat162_rn(a, b);   // x=a (low), y=b (high)
    return *(uint32_t*)&p;
}

#define MMA_BF16(c, a0, a1, a2, a3, b0, b1)                                   \
    asm volatile(                                                             \
        "mma.sync.aligned.m16n8k16.row.col.f32.bf16.bf16.f32 "                \
        "{%0,%1,%2,%3}, {%4,%5,%6,%7}, {%8,%9}, {%0,%1,%2,%3};"               \
        : "+f"((c)[0]), "+f"((c)[1]), "+f"((c)[2]), "+f"((c)[3])              \
        : "r"(a0), "r"(a1), "r"(a2), "r"(a3), "r"(b0), "r"(b1))

// ---------------------------------------------------------------------------
// 3) Tensor-core GEMM via mma.sync (HMMA): h = x @ W^T, 3-term bf16 split.
//    A = x tile (64 rows x 64 k) hi/lo bf16 in smem; B = W [n][k] hi/lo.
//    Warp computes 16 rows x 64 cols: 3 terms x 8 n-tiles x 4 k-steps = 96 MMA.
//    Epilogue: dinv = rsqrt(deg) (fused), h stored, out = h*dinv^2 + b
//    (self-loop + bias; fully initializes the poisoned output buffer).
// ---------------------------------------------------------------------------
__global__ __launch_bounds__(128)
void gemm_mma_kernel(const float* __restrict__ x,
                     const float* __restrict__ W,
                     const float* __restrict__ bias,
                     float* __restrict__ out, int N) {
    __shared__ uint32_t Ah[TILE * PITCH], Al[TILE * PITCH];
    __shared__ uint32_t Bh[D * PITCH],   Bl[D * PITCH];

    int tid = threadIdx.x;
    int base = blockIdx.x * TILE;
    int rows = N - base; if (rows > TILE) rows = TILE;

    // A fill: coalesced float4 reads, bf16 hi/lo split
    const float4* xg = (const float4*)(x + (size_t)base * D);
    for (int t = tid; t < rows * 16; t += 128) {
        int r = t >> 4, j = t & 15;
        float4 v = xg[t];
        float hx = __bfloat162float(__float2bfloat16(v.x));
        float hy = __bfloat162float(__float2bfloat16(v.y));
        float hz = __bfloat162float(__float2bfloat16(v.z));
        float hw = __bfloat162float(__float2bfloat16(v.w));
        Ah[r * PITCH + 2 * j]     = pack_bf(v.x, v.y);
        Ah[r * PITCH + 2 * j + 1] = pack_bf(v.z, v.w);
        Al[r * PITCH + 2 * j]     = pack_bf(v.x - hx, v.y - hy);
        Al[r * PITCH + 2 * j + 1] = pack_bf(v.z - hz, v.w - hw);
    }

    // B fill: W is [o][k] row-major = exactly the [n][k] layout mma "col" wants
    const float4* wg = (const float4*)W;
    for (int t = tid; t < D * 16; t += 128) {
        int o = t >> 4, j = t & 15;
        float4 v = wg[t];
        float hx = __bfloat162float(__float2bfloat16(v.x));
        float hy = __bfloat162float(__float2bfloat16(v.y));
        float hz = __bfloat162float(__float2bfloat16(v.z));
        float hw = __bfloat162float(__float2bfloat16(v.w));
        Bh[o * PITCH + 2 * j]     = pack_bf(v.x, v.y);
        Bh[o * PITCH + 2 * j + 1] = pack_bf(v.z, v.w);
        Bl[o * PITCH + 2 * j]     = pack_bf(v.x - hx, v.y - hy);
        Bl[o * PITCH + 2 * j + 1] = pack_bf(v.z - hz, v.w - hw);
    }
    __syncthreads();

    int lane = tid & 31;
    int w    = tid >> 5;          // warp 0..3 -> local rows w*16..w*16+15
    int g    = lane >> 2;         // group id (row within m16 / col within n8)
    int kq   = lane & 3;
    int rb   = w * 16;

    float c[8][4];
#pragma unroll
    for (int t = 0; t < 8; t++)
#pragma unroll
        for (int i = 0; i < 4; i++) c[t][i] = 0.f;

#pragma unroll
    for (int s = 0; s < 4; s++) {
        int ko = s * 8 + kq;
        // A fragments (reg order: {row g,k lo},{row g+8,k lo},{row g,k hi},{row g+8,k hi})
        uint32_t ah0 = Ah[(rb + g) * PITCH + ko];
        uint32_t ah1 = Ah[(rb + g + 8) * PITCH + ko];
        uint32_t ah2 = Ah[(rb + g) * PITCH + ko + 4];
        uint32_t ah3 = Ah[(rb + g + 8) * PITCH + ko + 4];
        uint32_t al0 = Al[(rb + g) * PITCH + ko];
        uint32_t al1 = Al[(rb + g + 8) * PITCH + ko];
        uint32_t al2 = Al[(rb + g) * PITCH + ko + 4];
        uint32_t al3 = Al[(rb + g + 8) * PITCH + ko + 4];
#pragma unroll
        for (int t = 0; t < 8; t++) {
            int nr = t * 8 + g;
            uint32_t bh0 = Bh[nr * PITCH + ko];
            uint32_t bh1 = Bh[nr * PITCH + ko + 4];
            uint32_t bl0 = Bl[nr * PITCH + ko];
            uint32_t bl1 = Bl[nr * PITCH + ko + 4];
            MMA_BF16(c[t], ah0, ah1, ah2, ah3, bh0, bh1);   // hi*hi
            MMA_BF16(c[t], ah0, ah1, ah2, ah3, bl0, bl1);   // hi*lo
            MMA_BF16(c[t], al0, al1, al2, al3, bh0, bh1);   // lo*hi
        }
    }

    // Epilogue: rows r0 = base+rb+g, r1 = r0+8; cols t*8 + kq*2 + {0,1}
    int r0 = base + rb + g;
    int r1 = r0 + 8;
    bool v0 = (r0 < N), v1 = (r1 < N);
    float dv0 = v0 ? rsqrtf(g_deg[r0]) : 0.f;
    float dv1 = v1 ? rsqrtf(g_deg[r1]) : 0.f;
    if (kq == 0 && v0) g_dinv[r0] = dv0;
    if (kq == 0 && v1) g_dinv[r1] = dv1;
    float sl0 = dv0 * dv0, sl1 = dv1 * dv1;

    const float2* b2 = (const float2*)bias;
    float2* h2 = (float2*)g_h;
    float2* o2 = (float2*)out;
#pragma unroll
    for (int t = 0; t < 8; t++) {
        int col2 = t * 4 + kq;            // float2 column index
        float2 bb = __ldg(&b2[col2]);
        if (v0) {
            h2[(size_t)r0 * 32 + col2] = make_float2(c[t][0], c[t][1]);
            o2[(size_t)r0 * 32 + col2] =
                make_float2(fmaf(c[t][0], sl0, bb.x), fmaf(c[t][1], sl0, bb.y));
        }
        if (v1) {
            h2[(size_t)r1 * 32 + col2] = make_float2(c[t][2], c[t][3]);
            o2[(size_t)r1 * 32 + col2] =
                make_float2(fmaf(c[t][2], sl1, bb.x), fmaf(c[t][3], sl1, bb.y));
        }
    }
}

// ---------------------------------------------------------------------------
// 4) Edge scatter (unchanged, measured 65 us REDG-rate floor)
// ---------------------------------------------------------------------------
__global__ __launch_bounds__(256)
void scatter_kernel(const int* __restrict__ ei,
                    float* __restrict__ out, int E) {
    long long gid = (long long)blockIdx.x * blockDim.x + threadIdx.x;
    int e = (int)(gid >> 4);
    int l = (int)(gid & 15);
    if (e >= E) return;

    int s = __ldg(&ei[e]);
    int d = __ldg(&ei[E + e]);
    float norm = g_dinv[s] * g_dinv[d];

    float4 v = ((const float4*)g_h)[(size_t)s * 16 + l];
    v.x *= norm; v.y *= norm; v.z *= norm; v.w *= norm;

    float* o = out + ((size_t)d * D + l * 4);
    asm volatile("red.global.add.v4.f32 [%0], {%1, %2, %3, %4};"
                 :: "l"(o), "f"(v.x), "f"(v.y), "f"(v.z), "f"(v.w)
                 : "memory");
}

// ---------------------------------------------------------------------------
extern "C" void kernel_launch(void* const* d_in, const int* in_sizes, int n_in,
                              void* d_out, int out_size) {
    const float* x  = (const float*)d_in[0];
    const int*   ei = (const int*)d_in[1];
    const float* W  = (const float*)d_in[2];
    const float* b  = (const float*)d_in[3];
    float*       out = (float*)d_out;

    int N = in_sizes[0] / D;   // 100000
    int E = in_sizes[1] / 2;   // 1000000

    int N4 = N / 4;
    deg_init_kernel<<<(N4 + 255) / 256, 256>>>(N4);
    deg_acc_kernel<<<(E + 255) / 256, 256>>>(ei, E);
    gemm_mma_kernel<<<(N + TILE - 1) / TILE, 128>>>(x, W, b, out, N);

    long long total = (long long)E * 16;
    int nb_s = (int)((total + 255) / 256);
    scatter_kernel<<<nb_s, 256>>>(ei, out, E);
}

// round 13
// speedup vs baseline: 1.5901x; 1.5217x over previous
#include <cuda_runtime.h>
#include <cuda_bf16.h>
#include <cstdint>

#define MAX_N 100000
#define MAX_E 1000000
#define D 64
#define TILE 64
#define PITCH 36

// Scratch (device globals: sanctioned alternative to cudaMalloc)
__device__ float g_hs[MAX_N * D];    // hs = dinv[n] * (x @ W^T)[n]  (prescaled)
__device__ float g_dinv[MAX_N];
__device__ int   g_cnt[MAX_N];       // in-degree (excl. self-loop)
__device__ int   g_start[MAX_N];     // CSR row starts
__device__ int   g_cursor[MAX_N];
__device__ int   g_ebuf[MAX_E];      // src per edge, bucketed by dst
__device__ int   g_bsum[128];

// ---------------------------------------------------------------------------
__global__ void zero_cnt_kernel(int N) {
    int i = blockIdx.x * blockDim.x + threadIdx.x;
    if (i < N) g_cnt[i] = 0;
}

__global__ void deg_acc_kernel(const int* __restrict__ ei, int E) {
    int e = blockIdx.x * blockDim.x + threadIdx.x;
    if (e < E) {
        int d = ei[E + e];
        asm volatile("red.global.add.s32 [%0], %1;"
                     :: "l"(&g_cnt[d]), "r"(1) : "memory");
    }
}

// two-level exclusive scan: g_cnt -> g_start (+cursor, +dinv in scan3)
__global__ __launch_bounds__(1024)
void scan1_kernel(int N) {
    __shared__ int wsum[32];
    int i = blockIdx.x * 1024 + threadIdx.x;
    int lane = threadIdx.x & 31, wid = threadIdx.x >> 5;
    int v = (i < N) ? g_cnt[i] : 0;
    int val = v;
#pragma unroll
    for (int off = 1; off < 32; off <<= 1) {
        int t = __shfl_up_sync(0xffffffffu, val, off);
        if (lane >= off) val += t;
    }
    if (lane == 31) wsum[wid] = val;
    __syncthreads();
    if (wid == 0) {
        int w = wsum[lane];
#pragma unroll
        for (int off = 1; off < 32; off <<= 1) {
            int t = __shfl_up_sync(0xffffffffu, w, off);
            if (lane >= off) w += t;
        }
        wsum[lane] = w;
    }
    __syncthreads();
    int incl = val + (wid > 0 ? wsum[wid - 1] : 0);
    if (i < N) g_start[i] = incl - v;
    if (threadIdx.x == 1023) g_bsum[blockIdx.x] = incl;
}

__global__ __launch_bounds__(128)
void scan2_kernel(int nb) {
    __shared__ int wsum[4];
    int lane = threadIdx.x & 31, wid = threadIdx.x >> 5;
    int v = (threadIdx.x < nb) ? g_bsum[threadIdx.x] : 0;
    int val = v;
#pragma unroll
    for (int off = 1; off < 32; off <<= 1) {
        int t = __shfl_up_sync(0xffffffffu, val, off);
        if (lane >= off) val += t;
    }
    if (lane == 31) wsum[wid] = val;
    __syncthreads();
    int pre = 0;
    for (int w = 0; w < wid; w++) pre += wsum[w];
    if (threadIdx.x < nb) g_bsum[threadIdx.x] = val - v + pre;
}

__global__ void scan3_kernel(int N) {
    int i = blockIdx.x * blockDim.x + threadIdx.x;
    if (i < N) {
        int s = g_start[i] + g_bsum[i >> 10];
        g_start[i]  = s;
        g_cursor[i] = s;
        g_dinv[i]   = rsqrtf(1.0f + (float)g_cnt[i]);
    }
}

__global__ void fill_kernel(const int* __restrict__ ei, int E) {
    int e = blockIdx.x * blockDim.x + threadIdx.x;
    if (e < E) {
        int s = ei[e];
        int d = ei[E + e];
        int pos = atomicAdd(&g_cursor[d], 1);
        g_ebuf[pos] = s;
    }
}

// ---------------------------------------------------------------------------
// Tensor-core GEMM via mma.sync (proven in R12): hs = dinv * (x @ W^T)
// ---------------------------------------------------------------------------
__device__ __forceinline__ uint32_t pack_bf(float a, float b) {
    __nv_bfloat162 p = __floats2bfloat162_rn(a, b);
    return *(uint32_t*)&p;
}

#define MMA_BF16(c, a0, a1, a2, a3, b0, b1)                                   \
    asm volatile(                                                             \
        "mma.sync.aligned.m16n8k16.row.col.f32.bf16.bf16.f32 "                \
        "{%0,%1,%2,%3}, {%4,%5,%6,%7}, {%8,%9}, {%0,%1,%2,%3};"               \
        : "+f"((c)[0]), "+f"((c)[1]), "+f"((c)[2]), "+f"((c)[3])              \
        : "r"(a0), "r"(a1), "r"(a2), "r"(a3), "r"(b0), "r"(b1))

__global__ __launch_bounds__(128)
void gemm_mma_kernel(const float* __restrict__ x,
                     const float* __restrict__ W, int N) {
    __shared__ uint32_t Ah[TILE * PITCH], Al[TILE * PITCH];
    __shared__ uint32_t Bh[D * PITCH],   Bl[D * PITCH];

    int tid = threadIdx.x;
    int base = blockIdx.x * TILE;
    int rows = N - base; if (rows > TILE) rows = TILE;

    const float4* xg = (const float4*)(x + (size_t)base * D);
    for (int t = tid; t < rows * 16; t += 128) {
        int r = t >> 4, j = t & 15;
        float4 v = xg[t];
        float hx = __bfloat162float(__float2bfloat16(v.x));
        float hy = __bfloat162float(__float2bfloat16(v.y));
        float hz = __bfloat162float(__float2bfloat16(v.z));
        float hw = __bfloat162float(__float2bfloat16(v.w));
        Ah[r * PITCH + 2 * j]     = pack_bf(v.x, v.y);
        Ah[r * PITCH + 2 * j + 1] = pack_bf(v.z, v.w);
        Al[r * PITCH + 2 * j]     = pack_bf(v.x - hx, v.y - hy);
        Al[r * PITCH + 2 * j + 1] = pack_bf(v.z - hz, v.w - hw);
    }
    const float4* wg = (const float4*)W;
    for (int t = tid; t < D * 16; t += 128) {
        int o = t >> 4, j = t & 15;
        float4 v = wg[t];
        float hx = __bfloat162float(__float2bfloat16(v.x));
        float hy = __bfloat162float(__float2bfloat16(v.y));
        float hz = __bfloat162float(__float2bfloat16(v.z));
        float hw = __bfloat162float(__float2bfloat16(v.w));
        Bh[o * PITCH + 2 * j]     = pack_bf(v.x, v.y);
        Bh[o * PITCH + 2 * j + 1] = pack_bf(v.z, v.w);
        Bl[o * PITCH + 2 * j]     = pack_bf(v.x - hx, v.y - hy);
        Bl[o * PITCH + 2 * j + 1] = pack_bf(v.z - hz, v.w - hw);
    }
    __syncthreads();

    int lane = tid & 31;
    int w    = tid >> 5;
    int g    = lane >> 2;
    int kq   = lane & 3;
    int rb   = w * 16;

    float c[8][4];
#pragma unroll
    for (int t = 0; t < 8; t++)
#pragma unroll
        for (int i = 0; i < 4; i++) c[t][i] = 0.f;

#pragma unroll
    for (int s = 0; s < 4; s++) {
        int ko = s * 8 + kq;
        uint32_t ah0 = Ah[(rb + g) * PITCH + ko];
        uint32_t ah1 = Ah[(rb + g + 8) * PITCH + ko];
        uint32_t ah2 = Ah[(rb + g) * PITCH + ko + 4];
        uint32_t ah3 = Ah[(rb + g + 8) * PITCH + ko + 4];
        uint32_t al0 = Al[(rb + g) * PITCH + ko];
        uint32_t al1 = Al[(rb + g + 8) * PITCH + ko];
        uint32_t al2 = Al[(rb + g) * PITCH + ko + 4];
        uint32_t al3 = Al[(rb + g + 8) * PITCH + ko + 4];
#pragma unroll
        for (int t = 0; t < 8; t++) {
            int nr = t * 8 + g;
            uint32_t bh0 = Bh[nr * PITCH + ko];
            uint32_t bh1 = Bh[nr * PITCH + ko + 4];
            uint32_t bl0 = Bl[nr * PITCH + ko];
            uint32_t bl1 = Bl[nr * PITCH + ko + 4];
            MMA_BF16(c[t], ah0, ah1, ah2, ah3, bh0, bh1);
            MMA_BF16(c[t], ah0, ah1, ah2, ah3, bl0, bl1);
            MMA_BF16(c[t], al0, al1, al2, al3, bh0, bh1);
        }
    }

    // Epilogue: hs = dinv * h  (prescaled for the gather)
    int r0 = base + rb + g;
    int r1 = r0 + 8;
    bool v0 = (r0 < N), v1 = (r1 < N);
    float dv0 = v0 ? g_dinv[r0] : 0.f;
    float dv1 = v1 ? g_dinv[r1] : 0.f;

    float2* h2 = (float2*)g_hs;
#pragma unroll
    for (int t = 0; t < 8; t++) {
        int col2 = t * 4 + kq;
        if (v0) h2[(size_t)r0 * 32 + col2] = make_float2(dv0 * c[t][0], dv0 * c[t][1]);
        if (v1) h2[(size_t)r1 * 32 + col2] = make_float2(dv1 * c[t][2], dv1 * c[t][3]);
    }
}

// ---------------------------------------------------------------------------
// Gather: one warp per node, lane owns one float2 column pair.
//   out[n] = b + dinv[n] * (hs[n] + sum_{s in in(n)} hs[s])
// Edge srcs batch-loaded 32 at a time (one coalesced LDG), broadcast by shfl;
// h loads 4-deep unrolled for MLP. No atomics; out written exactly once.
// ---------------------------------------------------------------------------
__global__ __launch_bounds__(256)
void gather_kernel(const float* __restrict__ bias,
                   float* __restrict__ out, int N) {
    int warp = (blockIdx.x * 256 + threadIdx.x) >> 5;
    int lane = threadIdx.x & 31;
    if (warp >= N) return;
    int n = warp;

    int start = g_start[n];
    int cnt   = g_cnt[n];

    const float2* hs2 = (const float2*)g_hs;

    float2 a0 = hs2[(size_t)n * 32 + lane];   // self-loop term
    float2 a1 = make_float2(0.f, 0.f);
    float2 a2 = make_float2(0.f, 0.f);
    float2 a3 = make_float2(0.f, 0.f);

    int i = 0;
    while (i < cnt) {
        int bc = cnt - i; if (bc > 32) bc = 32;
        int v = (lane < bc) ? g_ebuf[start + i + lane] : 0;  // coalesced
        int j = 0;
        for (; j + 4 <= bc; j += 4) {
            int s0 = __shfl_sync(0xffffffffu, v, j);
            int s1 = __shfl_sync(0xffffffffu, v, j + 1);
            int s2 = __shfl_sync(0xffffffffu, v, j + 2);
            int s3 = __shfl_sync(0xffffffffu, v, j + 3);
            float2 x0 = hs2[(size_t)s0 * 32 + lane];
            float2 x1 = hs2[(size_t)s1 * 32 + lane];
            float2 x2 = hs2[(size_t)s2 * 32 + lane];
            float2 x3 = hs2[(size_t)s3 * 32 + lane];
            a0.x += x0.x; a0.y += x0.y;
            a1.x += x1.x; a1.y += x1.y;
            a2.x += x2.x; a2.y += x2.y;
            a3.x += x3.x; a3.y += x3.y;
        }
        for (; j < bc; j++) {
            int s0 = __shfl_sync(0xffffffffu, v, j);
            float2 x0 = hs2[(size_t)s0 * 32 + lane];
            a0.x += x0.x; a0.y += x0.y;
        }
        i += bc;
    }
    a0.x += (a1.x + a2.x) + a3.x;
    a0.y += (a1.y + a2.y) + a3.y;

    float dn = g_dinv[n];
    float2 bb = ((const float2*)bias)[lane];
    float2 o;
    o.x = fmaf(dn, a0.x, bb.x);
    o.y = fmaf(dn, a0.y, bb.y);
    ((float2*)out)[(size_t)n * 32 + lane] = o;
}

// ---------------------------------------------------------------------------
extern "C" void kernel_launch(void* const* d_in, const int* in_sizes, int n_in,
                              void* d_out, int out_size) {
    const float* x  = (const float*)d_in[0];
    const int*   ei = (const int*)d_in[1];
    const float* W  = (const float*)d_in[2];
    const float* b  = (const float*)d_in[3];
    float*       out = (float*)d_out;

    int N = in_sizes[0] / D;   // 100000
    int E = in_sizes[1] / 2;   // 1000000
    int nb = (N + 1023) / 1024;

    zero_cnt_kernel<<<(N + 255) / 256, 256>>>(N);
    deg_acc_kernel<<<(E + 255) / 256, 256>>>(ei, E);
    scan1_kernel<<<nb, 1024>>>(N);
    scan2_kernel<<<1, 128>>>(nb);
    scan3_kernel<<<(N + 255) / 256, 256>>>(N);
    fill_kernel<<<(E + 255) / 256, 256>>>(ei, E);
    gemm_mma_kernel<<<(N + TILE - 1) / TILE, 128>>>(x, W, N);
    gather_kernel<<<(N * 32 + 255) / 256, 256>>>(b, out, N);
}

// round 14
// speedup vs baseline: 1.6241x; 1.0214x over previous
#include <cuda_runtime.h>
#include <cuda_bf16.h>
#include <cstdint>

#define MAX_N 100000
#define MAX_E 1000000
#define D 64
#define TILE 64
#define PITCH 36

// Scratch (device globals: sanctioned alternative to cudaMalloc).
// INVARIANT: g_cnt is all-zero at kernel_launch entry (zero-initialized at
// module load; gather_kernel re-zeroes it after use every call).
__device__ float g_hs[MAX_N * D];    // hs = dinv[n] * (x @ W^T)[n]  (prescaled)
__device__ float g_dinv[MAX_N];
__device__ int   g_cnt[MAX_N];       // in-degree (excl. self-loop)
__device__ int   g_start[MAX_N];     // CSR row starts
__device__ int   g_cursor[MAX_N];
__device__ int   g_ebuf[MAX_E];      // src per edge, bucketed by dst
__device__ int   g_bsum[128];

// ---------------------------------------------------------------------------
__global__ void deg_acc_kernel(const int* __restrict__ ei, int E) {
    int e = blockIdx.x * blockDim.x + threadIdx.x;
    if (e < E) {
        int d = ei[E + e];
        asm volatile("red.global.add.s32 [%0], %1;"
                     :: "l"(&g_cnt[d]), "r"(1) : "memory");
    }
}

// level-1 scan: per-1024 block scans + block sums
__global__ __launch_bounds__(1024)
void scan1_kernel(int N) {
    __shared__ int wsum[32];
    int i = blockIdx.x * 1024 + threadIdx.x;
    int lane = threadIdx.x & 31, wid = threadIdx.x >> 5;
    int v = (i < N) ? g_cnt[i] : 0;
    int val = v;
#pragma unroll
    for (int off = 1; off < 32; off <<= 1) {
        int t = __shfl_up_sync(0xffffffffu, val, off);
        if (lane >= off) val += t;
    }
    if (lane == 31) wsum[wid] = val;
    __syncthreads();
    if (wid == 0) {
        int w = wsum[lane];
#pragma unroll
        for (int off = 1; off < 32; off <<= 1) {
            int t = __shfl_up_sync(0xffffffffu, w, off);
            if (lane >= off) w += t;
        }
        wsum[lane] = w;
    }
    __syncthreads();
    int incl = val + (wid > 0 ? wsum[wid - 1] : 0);
    if (i < N) g_start[i] = incl - v;
    if (threadIdx.x == 1023) g_bsum[blockIdx.x] = incl;
}

// fused level-2 scan + finalize: each block's warp 0 redundantly scans bsum
// (nb <= 98 values — trivial), then all threads finalize start/cursor/dinv.
__global__ __launch_bounds__(256)
void scan23_kernel(int N, int nb) {
    __shared__ int pre[128];
    int tid = threadIdx.x;
    if (tid < 32) {
        int run = 0;
        for (int b = 0; b < nb; b += 32) {
            int idx = b + tid;
            int v = (idx < nb) ? g_bsum[idx] : 0;
            int val = v;
#pragma unroll
            for (int off = 1; off < 32; off <<= 1) {
                int t = __shfl_up_sync(0xffffffffu, val, off);
                if (tid >= off) val += t;
            }
            if (idx < 128) pre[idx] = run + val - v;   // exclusive
            run += __shfl_sync(0xffffffffu, val, 31);
        }
    }
    __syncthreads();
    int i = blockIdx.x * 256 + tid;
    if (i < N) {
        int s = g_start[i] + pre[i >> 10];
        g_start[i]  = s;
        g_cursor[i] = s;
        g_dinv[i]   = rsqrtf(1.0f + (float)g_cnt[i]);
    }
}

__global__ void fill_kernel(const int* __restrict__ ei, int E) {
    int e = blockIdx.x * blockDim.x + threadIdx.x;
    if (e < E) {
        int s = ei[e];
        int d = ei[E + e];
        int pos = atomicAdd(&g_cursor[d], 1);
        g_ebuf[pos] = s;
    }
}

// ---------------------------------------------------------------------------
// Tensor-core GEMM via mma.sync (proven R12/R13): hs = dinv * (x @ W^T)
// ---------------------------------------------------------------------------
__device__ __forceinline__ uint32_t pack_bf(float a, float b) {
    __nv_bfloat162 p = __floats2bfloat162_rn(a, b);
    return *(uint32_t*)&p;
}

#define MMA_BF16(c, a0, a1, a2, a3, b0, b1)                                   \
    asm volatile(                                                             \
        "mma.sync.aligned.m16n8k16.row.col.f32.bf16.bf16.f32 "                \
        "{%0,%1,%2,%3}, {%4,%5,%6,%7}, {%8,%9}, {%0,%1,%2,%3};"               \
        : "+f"((c)[0]), "+f"((c)[1]), "+f"((c)[2]), "+f"((c)[3])              \
        : "r"(a0), "r"(a1), "r"(a2), "r"(a3), "r"(b0), "r"(b1))

__global__ __launch_bounds__(128)
void gemm_mma_kernel(const float* __restrict__ x,
                     const float* __restrict__ W, int N) {
    __shared__ uint32_t Ah[TILE * PITCH], Al[TILE * PITCH];
    __shared__ uint32_t Bh[D * PITCH],   Bl[D * PITCH];

    int tid = threadIdx.x;
    int base = blockIdx.x * TILE;
    int rows = N - base; if (rows > TILE) rows = TILE;

    const float4* xg = (const float4*)(x + (size_t)base * D);
    for (int t = tid; t < rows * 16; t += 128) {
        int r = t >> 4, j = t & 15;
        float4 v = xg[t];
        float hx = __bfloat162float(__float2bfloat16(v.x));
        float hy = __bfloat162float(__float2bfloat16(v.y));
        float hz = __bfloat162float(__float2bfloat16(v.z));
        float hw = __bfloat162float(__float2bfloat16(v.w));
        Ah[r * PITCH + 2 * j]     = pack_bf(v.x, v.y);
        Ah[r * PITCH + 2 * j + 1] = pack_bf(v.z, v.w);
        Al[r * PITCH + 2 * j]     = pack_bf(v.x - hx, v.y - hy);
        Al[r * PITCH + 2 * j + 1] = pack_bf(v.z - hz, v.w - hw);
    }
    const float4* wg = (const float4*)W;
    for (int t = tid; t < D * 16; t += 128) {
        int o = t >> 4, j = t & 15;
        float4 v = wg[t];
        float hx = __bfloat162float(__float2bfloat16(v.x));
        float hy = __bfloat162float(__float2bfloat16(v.y));
        float hz = __bfloat162float(__float2bfloat16(v.z));
        float hw = __bfloat162float(__float2bfloat16(v.w));
        Bh[o * PITCH + 2 * j]     = pack_bf(v.x, v.y);
        Bh[o * PITCH + 2 * j + 1] = pack_bf(v.z, v.w);
        Bl[o * PITCH + 2 * j]     = pack_bf(v.x - hx, v.y - hy);
        Bl[o * PITCH + 2 * j + 1] = pack_bf(v.z - hz, v.w - hw);
    }
    __syncthreads();

    int lane = tid & 31;
    int w    = tid >> 5;
    int g    = lane >> 2;
    int kq   = lane & 3;
    int rb   = w * 16;

    float c[8][4];
#pragma unroll
    for (int t = 0; t < 8; t++)
#pragma unroll
        for (int i = 0; i < 4; i++) c[t][i] = 0.f;

#pragma unroll
    for (int s = 0; s < 4; s++) {
        int ko = s * 8 + kq;
        uint32_t ah0 = Ah[(rb + g) * PITCH + ko];
        uint32_t ah1 = Ah[(rb + g + 8) * PITCH + ko];
        uint32_t ah2 = Ah[(rb + g) * PITCH + ko + 4];
        uint32_t ah3 = Ah[(rb + g + 8) * PITCH + ko + 4];
        uint32_t al0 = Al[(rb + g) * PITCH + ko];
        uint32_t al1 = Al[(rb + g + 8) * PITCH + ko];
        uint32_t al2 = Al[(rb + g) * PITCH + ko + 4];
        uint32_t al3 = Al[(rb + g + 8) * PITCH + ko + 4];
#pragma unroll
        for (int t = 0; t < 8; t++) {
            int nr = t * 8 + g;
            uint32_t bh0 = Bh[nr * PITCH + ko];
            uint32_t bh1 = Bh[nr * PITCH + ko + 4];
            uint32_t bl0 = Bl[nr * PITCH + ko];
            uint32_t bl1 = Bl[nr * PITCH + ko + 4];
            MMA_BF16(c[t], ah0, ah1, ah2, ah3, bh0, bh1);
            MMA_BF16(c[t], ah0, ah1, ah2, ah3, bl0, bl1);
            MMA_BF16(c[t], al0, al1, al2, al3, bh0, bh1);
        }
    }

    int r0 = base + rb + g;
    int r1 = r0 + 8;
    bool v0 = (r0 < N), v1 = (r1 < N);
    float dv0 = v0 ? g_dinv[r0] : 0.f;
    float dv1 = v1 ? g_dinv[r1] : 0.f;

    float2* h2 = (float2*)g_hs;
#pragma unroll
    for (int t = 0; t < 8; t++) {
        int col2 = t * 4 + kq;
        if (v0) h2[(size_t)r0 * 32 + col2] = make_float2(dv0 * c[t][0], dv0 * c[t][1]);
        if (v1) h2[(size_t)r1 * 32 + col2] = make_float2(dv1 * c[t][2], dv1 * c[t][3]);
    }
}

// ---------------------------------------------------------------------------
// Gather: one warp per node, lane owns one float2 column pair.
//   out[n] = b + dinv[n] * (hs[n] + sum_{s in in(n)} hs[s])
// Edge srcs batch-loaded 32 at a time (coalesced), broadcast by shfl;
// hs loads 4-deep unrolled. No atomics; out written exactly once.
// Tail: zero g_cnt[n] to restore the entry invariant for the next call.
// ---------------------------------------------------------------------------
__global__ __launch_bounds__(256)
void gather_kernel(const float* __restrict__ bias,
                   float* __restrict__ out, int N) {
    int warp = (blockIdx.x * 256 + threadIdx.x) >> 5;
    int lane = threadIdx.x & 31;
    if (warp >= N) return;
    int n = warp;

    int start = g_start[n];
    int cnt   = g_cnt[n];

    const float2* hs2 = (const float2*)g_hs;

    float2 a0 = hs2[(size_t)n * 32 + lane];   // self-loop term
    float2 a1 = make_float2(0.f, 0.f);
    float2 a2 = make_float2(0.f, 0.f);
    float2 a3 = make_float2(0.f, 0.f);

    int i = 0;
    while (i < cnt) {
        int bc = cnt - i; if (bc > 32) bc = 32;
        int v = (lane < bc) ? g_ebuf[start + i + lane] : 0;  // coalesced
        int j = 0;
        for (; j + 4 <= bc; j += 4) {
            int s0 = __shfl_sync(0xffffffffu, v, j);
            int s1 = __shfl_sync(0xffffffffu, v, j + 1);
            int s2 = __shfl_sync(0xffffffffu, v, j + 2);
            int s3 = __shfl_sync(0xffffffffu, v, j + 3);
            float2 x0 = hs2[(size_t)s0 * 32 + lane];
            float2 x1 = hs2[(size_t)s1 * 32 + lane];
            float2 x2 = hs2[(size_t)s2 * 32 + lane];
            float2 x3 = hs2[(size_t)s3 * 32 + lane];
            a0.x += x0.x; a0.y += x0.y;
            a1.x += x1.x; a1.y += x1.y;
            a2.x += x2.x; a2.y += x2.y;
            a3.x += x3.x; a3.y += x3.y;
        }
        for (; j < bc; j++) {
            int s0 = __shfl_sync(0xffffffffu, v, j);
            float2 x0 = hs2[(size_t)s0 * 32 + lane];
            a0.x += x0.x; a0.y += x0.y;
        }
        i += bc;
    }
    a0.x += (a1.x + a2.x) + a3.x;
    a0.y += (a1.y + a2.y) + a3.y;

    float dn = g_dinv[n];
    float2 bb = ((const float2*)bias)[lane];
    float2 o;
    o.x = fmaf(dn, a0.x, bb.x);
    o.y = fmaf(dn, a0.y, bb.y);
    ((float2*)out)[(size_t)n * 32 + lane] = o;

    if (lane == 0) g_cnt[n] = 0;   // restore invariant for next call
}

// ---------------------------------------------------------------------------
extern "C" void kernel_launch(void* const* d_in, const int* in_sizes, int n_in,
                              void* d_out, int out_size) {
    const float* x  = (const float*)d_in[0];
    const int*   ei = (const int*)d_in[1];
    const float* W  = (const float*)d_in[2];
    const float* b  = (const float*)d_in[3];
    float*       out = (float*)d_out;

    int N = in_sizes[0] / D;   // 100000
    int E = in_sizes[1] / 2;   // 1000000
    int nb = (N + 1023) / 1024;

    deg_acc_kernel<<<(E + 255) / 256, 256>>>(ei, E);
    scan1_kernel<<<nb, 1024>>>(N);
    scan23_kernel<<<(N + 255) / 256, 256>>>(N, nb);
    fill_kernel<<<(E + 255) / 256, 256>>>(ei, E);
    gemm_mma_kernel<<<(N + TILE - 1) / TILE, 128>>>(x, W, N);
    gather_kernel<<<(N * 32 + 255) / 256, 256>>>(b, out, N);
}